// round 2
// baseline (speedup 1.0000x reference)
#include <cuda_runtime.h>
#include <math.h>

#define HD 64
#define NE 1024
#define TT 4096
#define NB 4
#define BT (NB*TT)
#define BQ 32     // q rows per tile (attention)
#define BK 64     // kv rows per tile

// Scratch for projected q,k,v (12 MB total) — device globals (no allocs allowed)
__device__ float g_q[BT*HD];
__device__ float g_k[BT*HD];
__device__ float g_v[BT*HD];

typedef unsigned long long u64;

// Packed fp32x2 FMA (Blackwell FFMA2 — only reachable via PTX)
__device__ __forceinline__ u64 ffma2(u64 a, u64 b, u64 c) {
    u64 d;
    asm("fma.rn.f32x2 %0, %1, %2, %3;" : "=l"(d) : "l"(a), "l"(b), "l"(c));
    return d;
}
__device__ __forceinline__ u64 pack2(float x, float y) {
    union { float2 f; u64 u; } t; t.f = make_float2(x, y); return t.u;
}
__device__ __forceinline__ float2 unpack2(u64 a) {
    union { float2 f; u64 u; } t; t.u = a; return t.f;
}

// ---------------------------------------------------------------------------
// Kernel 1: fused QKV projection.  x[16384,1024] @ W{k,q,v}[1024,64].
// Block = 64 rows x 192 cols (k|q|v). 256 threads; warp owns 8 rows,
// lane owns 6 cols (3 packed col-pairs). K-chunks of 32 staged in smem.
// ---------------------------------------------------------------------------
__global__ __launch_bounds__(256, 2) void qkv_kernel(
    const float* __restrict__ x,
    const float* __restrict__ Wk,
    const float* __restrict__ Wq,
    const float* __restrict__ Wv)
{
    __shared__ float xs[64 * 32];     // x tile  [row][k]
    __shared__ float ws[32 * 192];    // W tile  [k][c]  c in [0,192)

    const int tid  = threadIdx.x;
    const int warp = tid >> 5;
    const int lane = tid & 31;
    const int row0 = blockIdx.x * 64;

    u64 acc[8][3];
    #pragma unroll
    for (int r = 0; r < 8; r++)
        #pragma unroll
        for (int j = 0; j < 3; j++) acc[r][j] = 0ull;

    for (int kk = 0; kk < NE; kk += 32) {
        __syncthreads();
        // stage x tile: 64 rows x 8 float4
        #pragma unroll
        for (int i = 0; i < 2; i++) {
            int idx = tid + i * 256;          // 0..511
            int r = idx >> 3, q4 = idx & 7;
            float4 v = *(const float4*)&x[(row0 + r) * NE + kk + q4 * 4];
            *(float4*)&xs[r * 32 + q4 * 4] = v;
        }
        // stage W tile: 32 rows x 48 float4 (k|q|v concatenated)
        #pragma unroll
        for (int i = 0; i < 6; i++) {
            int idx  = tid + i * 256;         // 0..1535
            int ccol = idx % 48;
            int k    = idx / 48;
            int c0   = ccol * 4;
            const float* W = (c0 < 64) ? Wk : (c0 < 128) ? Wq : Wv;
            float4 v = *(const float4*)&W[(kk + k) * HD + (c0 & 63)];
            *(float4*)&ws[k * 192 + c0] = v;
        }
        __syncthreads();

        #pragma unroll
        for (int k = 0; k < 32; k++) {
            u64 w0 = *(const u64*)&ws[k * 192 + lane * 6];
            u64 w1 = *(const u64*)&ws[k * 192 + lane * 6 + 2];
            u64 w2 = *(const u64*)&ws[k * 192 + lane * 6 + 4];
            #pragma unroll
            for (int rr = 0; rr < 8; rr++) {
                float xv = xs[(warp * 8 + rr) * 32 + k];
                u64 xb = pack2(xv, xv);
                acc[rr][0] = ffma2(xb, w0, acc[rr][0]);
                acc[rr][1] = ffma2(xb, w1, acc[rr][1]);
                acc[rr][2] = ffma2(xb, w2, acc[rr][2]);
            }
        }
    }

    const float qscale = 0.03125f;  // 1024^-0.5 folded into q
    #pragma unroll
    for (int rr = 0; rr < 8; rr++) {
        int row = row0 + warp * 8 + rr;
        #pragma unroll
        for (int j = 0; j < 3; j++) {
            int c   = lane * 6 + j * 2;     // even -> pair never crosses a matrix
            int mat = c >> 6;
            int h   = c & 63;
            float2 o = unpack2(acc[rr][j]);
            float* dst = (mat == 0) ? g_k : (mat == 1) ? g_q : g_v;
            if (mat == 1) { o.x *= qscale; o.y *= qscale; }
            *(float2*)&dst[row * HD + h] = o;
        }
    }
}

// ---------------------------------------------------------------------------
// Kernel 2: causal flash attention, fp32, packed-f32x2 math.
// Each CTA handles the q-tile PAIR (t, 127-t) of 32 rows each -> uniform
// 65 kv-iterations per CTA (perfect causal balance). BLOCK_N = 64.
// Warp owns 4 q rows; lane owns S cols {lane, lane+32} and O h-pair 2*lane.
// K/Q smem use pair-XOR swizzle; V/P plain. All accesses conflict-free.
// ---------------------------------------------------------------------------
__global__ __launch_bounds__(256, 2) void attn_kernel(float* __restrict__ out)
{
    __shared__ float Qs[BQ * HD];   // swizzled
    __shared__ float Ks[BK * HD];   // swizzled
    __shared__ float Vs[BK * HD];   // plain
    __shared__ float Ps[BQ * HD];   // plain (P = exp(S - m))

    const int tid  = threadIdx.x;
    const int warp = tid >> 5;
    const int lane = tid & 31;
    const int b    = blockIdx.y;
    const int base = b * TT * HD;
    const int pidx = blockIdx.x;           // 0..63

    for (int ti = 0; ti < 2; ti++) {
        const int t      = (ti == 0) ? pidx : (127 - pidx);
        const int n_iter = t / 2 + 1;
        const int r0     = t * BQ;

        __syncthreads();
        // load Q tile (swizzled): 32 rows x 32 float2
        #pragma unroll
        for (int i = 0; i < 4; i++) {
            int idx = tid + i * 256;       // 0..1023
            int r = idx >> 5, pp = idx & 31;
            float2 v = *(const float2*)&g_q[base + (r0 + r) * HD + pp * 2];
            *(float2*)&Qs[r * HD + 2 * (pp ^ (r & 31))] = v;
        }

        u64 o2[4] = {0ull, 0ull, 0ull, 0ull};
        float m[4], l[4];
        #pragma unroll
        for (int rr = 0; rr < 4; rr++) { m[rr] = -INFINITY; l[rr] = 0.f; }

        const int c0 = lane, c1 = lane + 32;

        for (int it = 0; it < n_iter; it++) {
            const int j0 = it * BK;
            // load K (swizzled) + V (plain): 64 rows x 32 float2 each
            #pragma unroll
            for (int i = 0; i < 8; i++) {
                int idx = tid + i * 256;   // 0..2047
                int r = idx >> 5, pp = idx & 31;
                float2 kv = *(const float2*)&g_k[base + (j0 + r) * HD + pp * 2];
                *(float2*)&Ks[r * HD + 2 * (pp ^ (r & 31))] = kv;
                float2 vv = *(const float2*)&g_v[base + (j0 + r) * HD + pp * 2];
                *(float2*)&Vs[r * HD + pp * 2] = vv;
            }
            __syncthreads();

            // ---- S = Q K^T  (packed partial sums over h) ----
            u64 s2[4][2] = {};
            #pragma unroll
            for (int pp = 0; pp < 32; pp++) {
                u64 k2a = *(const u64*)&Ks[c0 * HD + 2 * (pp ^ lane)];
                u64 k2b = *(const u64*)&Ks[c1 * HD + 2 * (pp ^ lane)];
                #pragma unroll
                for (int rr = 0; rr < 4; rr++) {
                    int r = warp * 4 + rr;
                    u64 q2 = *(const u64*)&Qs[r * HD + 2 * (pp ^ (r & 31))];
                    s2[rr][0] = ffma2(q2, k2a, s2[rr][0]);
                    s2[rr][1] = ffma2(q2, k2b, s2[rr][1]);
                }
            }

            // ---- online softmax (row owned by whole warp) ----
            const bool maskit = (it == n_iter - 1);
            #pragma unroll
            for (int rr = 0; rr < 4; rr++) {
                const int grow = r0 + warp * 4 + rr;
                float2 a  = unpack2(s2[rr][0]);
                float2 bb = unpack2(s2[rr][1]);
                float sA = a.x + a.y;
                float sB = bb.x + bb.y;
                if (maskit) {
                    if (j0 + c0 > grow) sA = -INFINITY;
                    if (j0 + c1 > grow) sB = -INFINITY;
                }
                float tmax = fmaxf(sA, sB);
                #pragma unroll
                for (int off = 16; off > 0; off >>= 1)
                    tmax = fmaxf(tmax, __shfl_xor_sync(0xffffffffu, tmax, off));
                float mnew = fmaxf(m[rr], tmax);
                float pA = __expf(sA - mnew);
                float pB = __expf(sB - mnew);
                float rsum = pA + pB;
                #pragma unroll
                for (int off = 16; off > 0; off >>= 1)
                    rsum += __shfl_xor_sync(0xffffffffu, rsum, off);
                float scale = __expf(m[rr] - mnew);
                l[rr] = l[rr] * scale + rsum;
                m[rr] = mnew;
                o2[rr] = ffma2(o2[rr], pack2(scale, scale), 0ull);
                Ps[(warp * 4 + rr) * HD + c0] = pA;
                Ps[(warp * 4 + rr) * HD + c1] = pB;
            }
            __syncthreads();

            // ---- O += P V  (packed over h; lane owns h-pair 2*lane) ----
            #pragma unroll
            for (int cc = 0; cc < 32; cc++) {
                int c = cc * 2;
                u64 v2a = *(const u64*)&Vs[c * HD + lane * 2];
                u64 v2b = *(const u64*)&Vs[(c + 1) * HD + lane * 2];
                #pragma unroll
                for (int rr = 0; rr < 4; rr++) {
                    float2 p2 = *(const float2*)&Ps[(warp * 4 + rr) * HD + c];
                    o2[rr] = ffma2(pack2(p2.x, p2.x), v2a, o2[rr]);
                    o2[rr] = ffma2(pack2(p2.y, p2.y), v2b, o2[rr]);
                }
            }
            __syncthreads();
        }

        // epilogue: O / l
        #pragma unroll
        for (int rr = 0; rr < 4; rr++) {
            float inv = 1.0f / l[rr];
            float2 o = unpack2(o2[rr]);
            o.x *= inv; o.y *= inv;
            int grow = r0 + warp * 4 + rr;
            *(float2*)&out[base + grow * HD + lane * 2] = o;
        }
    }
}

extern "C" void kernel_launch(void* const* d_in, const int* in_sizes, int n_in,
                              void* d_out, int out_size)
{
    const float* x  = (const float*)d_in[0];
    const float* Wk = (const float*)d_in[1];
    const float* Wq = (const float*)d_in[2];
    const float* Wv = (const float*)d_in[3];
    float* out = (float*)d_out;

    qkv_kernel<<<BT / 64, 256>>>(x, Wk, Wq, Wv);
    attn_kernel<<<dim3(64, NB), 256>>>(out);
}